// round 12
// baseline (speedup 1.0000x reference)
#include <cuda_runtime.h>
#include <cuda_fp16.h>
#include <cstdint>

#define Bv 128
#define Nv 512
#define Xv 128
#define Hv 256
#define BN (Bv*Nv)           // 65536
#define GSZ (BN*Hv)          // 16777216 floats per gate buffer

// 6 precomputed gate-input buffers: 0=fg_x 1=ig_x 2=in_x 3=og_x 4=tm1 5=tm2
__device__ float g_pre[6][GSZ];

__device__ __forceinline__ float sigmoidf_(float v) { return 1.0f / (1.0f + __expf(-v)); }

// exp-based tanh: ~5 instr, rel err ~1e-6. Args bounded, no overflow path.
__device__ __forceinline__ float tanh_fast_(float x) {
    float e = __expf(-2.0f * x);
    return __fdividef(1.0f - e, 1.0f + e);
}

__device__ __forceinline__ uint32_t smem_u32_(const void* p) {
    uint32_t a;
    asm("{ .reg .u64 t; cvta.to.shared.u64 t, %1; cvt.u32.u64 %0, t; }" : "=r"(a) : "l"(p));
    return a;
}

// ---- f32x2 packed-math helpers (precompute kernel) ----
__device__ __forceinline__ unsigned long long pack2_(float a) {
    unsigned long long r;
    asm("mov.b64 %0, {%1, %1};" : "=l"(r) : "f"(a));
    return r;
}
__device__ __forceinline__ void ffma2_(unsigned long long& d, unsigned long long a, unsigned long long b) {
    asm("fma.rn.f32x2 %0, %1, %2, %0;" : "+l"(d) : "l"(a), "l"(b));
}
__device__ __forceinline__ float2 unpack2_(unsigned long long v) {
    float lo, hi;
    asm("mov.b64 {%0, %1}, %2;" : "=f"(lo), "=f"(hi) : "l"(v));
    return make_float2(lo, hi);
}

// ---- tensor-core helpers (rec kernel) ----
__device__ __forceinline__ void ldsm4t_(uint32_t* d, uint32_t addr) {
    asm volatile("ldmatrix.sync.aligned.m8n8.x4.trans.shared.b16 {%0,%1,%2,%3}, [%4];"
        : "=r"(d[0]), "=r"(d[1]), "=r"(d[2]), "=r"(d[3]) : "r"(addr));
}
__device__ __forceinline__ void mma16816_(float* c, const uint32_t* a, const uint32_t* b) {
    asm volatile(
        "mma.sync.aligned.m16n8k16.row.col.f32.f16.f16.f32 "
        "{%0,%1,%2,%3}, {%4,%5,%6,%7}, {%8,%9}, {%0,%1,%2,%3};"
        : "+f"(c[0]), "+f"(c[1]), "+f"(c[2]), "+f"(c[3])
        : "r"(a[0]), "r"(a[1]), "r"(a[2]), "r"(a[3]), "r"(b[0]), "r"(b[1]));
}
// Split fp32 pair into hi-fp16x2 and lo-residual-fp16x2.
__device__ __forceinline__ void split2_(float2 v, uint32_t& hi, uint32_t& lo) {
    __half h0 = __float2half_rn(v.x), h1 = __float2half_rn(v.y);
    float r0 = v.x - __half2float(h0), r1 = v.y - __half2float(h1);
    __half2 H = __halves2half2(h0, h1);
    __half2 L = __floats2half2_rn(r0, r1);
    hi = *(uint32_t*)&H;
    lo = *(uint32_t*)&L;
}

// Bulk DSMEM copy: local smem src -> rank rk's smem dst (same-offset address
// space), crediting rank rk's mbarrier with complete_tx bytes.
__device__ __forceinline__ void bulk_copy_rank_(uint32_t dst, uint32_t src,
                                                uint32_t mb, uint32_t rank,
                                                uint32_t bytes) {
    asm volatile(
        "{\n\t"
        ".reg .b32 rd, rm;\n\t"
        "mapa.shared::cluster.u32 rd, %0, %3;\n\t"
        "mapa.shared::cluster.u32 rm, %2, %3;\n\t"
        "cp.async.bulk.shared::cluster.shared::cta.mbarrier::complete_tx::bytes [rd], [%1], %4, [rm];\n\t"
        "}"
        :: "r"(dst), "r"(src), "r"(mb), "r"(rank), "r"(bytes) : "memory");
}

#define MBAR_INIT_(a, c) \
    asm volatile("mbarrier.init.shared.b64 [%0], %1;" :: "r"(a), "r"(c) : "memory")

#define MBAR_ARRIVE_EXPECT_(a, bytes) \
    asm volatile("mbarrier.arrive.expect_tx.shared.b64 _, [%0], %1;" \
                 :: "r"(a), "r"(bytes) : "memory")

#define FENCE_ASYNC_() asm volatile("fence.proxy.async.shared::cta;" ::: "memory")

__device__ __forceinline__ void mbar_wait_(uint32_t a, uint32_t parity) {
    asm volatile(
        "{\n\t"
        ".reg .pred P;\n\t"
        "WL_%=:\n\t"
        "mbarrier.try_wait.parity.acquire.cta.shared::cta.b64 P, [%0], %1, 0x989680;\n\t"
        "@P bra.uni WD_%=;\n\t"
        "bra.uni WL_%=;\n\t"
        "WD_%=:\n\t"
        "}"
        :: "r"(a), "r"(parity) : "memory");
}

#define CLUSTER_SYNC_() do { \
    asm volatile("barrier.cluster.arrive.aligned;" ::: "memory"); \
    asm volatile("barrier.cluster.wait.aligned;"   ::: "memory"); \
} while (0)

#define BAR_SYNC_(id, cnt) \
    asm volatile("bar.sync %0, %1;" :: "r"(id), "r"(cnt) : "memory")

#define PREFETCH_L2_(p) \
    asm volatile("prefetch.global.L2 [%0];" :: "l"(p))

// ============================================================================
// Phase 1: precompute all input-dependent gate terms. (unchanged)
// grid (512 bn-tiles, 24 h-tiles of 64), block 256, 2 CTAs/SM.
// ============================================================================

#define XS_STRIDE 132
#define WS_STRIDE 68
#define PRE_SMEM_BYTES ((128 * XS_STRIDE + 128 * WS_STRIDE) * 4)   // 102400

__global__ void __launch_bounds__(256, 2) precompute_kernel(
    const float* __restrict__ x, const float* __restrict__ tvec,
    const float* __restrict__ fg_w_x, const float* __restrict__ fg_b,
    const float* __restrict__ ig_w_x, const float* __restrict__ ig_b,
    const float* __restrict__ in_w_x, const float* __restrict__ in_b,
    const float* __restrict__ og_w_x, const float* __restrict__ og_b, const float* __restrict__ og_w_t,
    const float* __restrict__ tg1_w_x, const float* __restrict__ tg1_b, const float* __restrict__ tg1_w_t,
    const float* __restrict__ tg2_w_x, const float* __restrict__ tg2_b, const float* __restrict__ tg2_w_t)
{
    extern __shared__ float sm[];
    float* xs = sm;                        // [128][132]
    float* ws = sm + 128 * XS_STRIDE;      // [128 k][68]

    const int tid  = threadIdx.x;
    const int bn0  = blockIdx.x * 128;
    const int ht   = blockIdx.y;
    const int gate = ht >> 2;
    const int hl0  = (ht & 3) * 64;

    const float* wptr; const float* bptr; const float* tptr = nullptr;
    switch (gate) {
        case 0:  wptr = fg_w_x;  bptr = fg_b;  break;
        case 1:  wptr = ig_w_x;  bptr = ig_b;  break;
        case 2:  wptr = in_w_x;  bptr = in_b;  break;
        case 3:  wptr = og_w_x;  bptr = og_b;  tptr = og_w_t;  break;
        case 4:  wptr = tg1_w_x; bptr = tg1_b; tptr = tg1_w_t; break;
        default: wptr = tg2_w_x; bptr = tg2_b; tptr = tg2_w_t; break;
    }

    for (int i = tid; i < 4096; i += 256) {
        int row = i >> 5, kq = i & 31;
        *(float4*)(xs + row * XS_STRIDE + kq * 4) =
            *(const float4*)(x + (size_t)(bn0 + row) * 128 + kq * 4);
    }
    for (int i = tid; i < 2048; i += 256) {
        int h = i >> 5, kq = i & 31;
        float4 v = *(const float4*)(wptr + (size_t)(hl0 + h) * 128 + kq * 4);
        ws[(kq * 4 + 0) * WS_STRIDE + h] = v.x;
        ws[(kq * 4 + 1) * WS_STRIDE + h] = v.y;
        ws[(kq * 4 + 2) * WS_STRIDE + h] = v.z;
        ws[(kq * 4 + 3) * WS_STRIDE + h] = v.w;
    }
    __syncthreads();

    const int trow = tid >> 3;   // 0..31
    const int tcol = tid & 7;    // 0..7

    unsigned long long acc2[4][4];
    #pragma unroll
    for (int i = 0; i < 4; i++) {
        #pragma unroll
        for (int q = 0; q < 4; q++) acc2[i][q] = 0ull;
    }

    #pragma unroll 2
    for (int k4 = 0; k4 < 32; ++k4) {
        float4 av[4];
        #pragma unroll
        for (int i = 0; i < 4; i++)
            av[i] = *(const float4*)(xs + (trow * 4 + i) * XS_STRIDE + k4 * 4);
        #pragma unroll
        for (int cc = 0; cc < 4; cc++) {
            const float* wr = ws + (k4 * 4 + cc) * WS_STRIDE + tcol * 8;
            ulonglong2 b01 = *(const ulonglong2*)(wr);
            ulonglong2 b23 = *(const ulonglong2*)(wr + 4);
            #pragma unroll
            for (int i = 0; i < 4; i++) {
                float a = (cc == 0) ? av[i].x : (cc == 1) ? av[i].y
                        : (cc == 2) ? av[i].z : av[i].w;
                unsigned long long aa = pack2_(a);
                ffma2_(acc2[i][0], aa, b01.x);
                ffma2_(acc2[i][1], aa, b01.y);
                ffma2_(acc2[i][2], aa, b23.x);
                ffma2_(acc2[i][3], aa, b23.y);
            }
        }
    }

    const int hgbase = hl0 + tcol * 8;
    float bias[8], tw[8];
    #pragma unroll
    for (int jj = 0; jj < 8; jj++) {
        bias[jj] = bptr[hgbase + jj];
        tw[jj]   = (tptr != nullptr) ? tptr[hgbase + jj] : 0.0f;
    }
    float* outg = &g_pre[gate][0];
    #pragma unroll
    for (int i = 0; i < 4; i++) {
        int row = bn0 + trow * 4 + i;
        float tv = (gate >= 3) ? tvec[row] : 0.0f;
        float oo[8];
        #pragma unroll
        for (int q = 0; q < 4; q++) {
            float2 u = unpack2_(acc2[i][q]);
            oo[2 * q]     = u.x;
            oo[2 * q + 1] = u.y;
        }
        float o[8];
        #pragma unroll
        for (int jj = 0; jj < 8; jj++) {
            float v;
            if (gate < 3)       v = oo[jj] + bias[jj];
            else if (gate == 3) v = oo[jj] + tw[jj] * tv + bias[jj];
            else                v = sigmoidf_(oo[jj] + tanhf(tw[jj] * tv) + bias[jj]);
            o[jj] = v;
        }
        float4* dst = (float4*)(outg + (size_t)row * 256 + hgbase);
        dst[0] = make_float4(o[0], o[1], o[2], o[3]);
        dst[1] = make_float4(o[4], o[5], o[6], o[7]);
    }
}

// ============================================================================
// Phase 2: recurrence via tensor cores, decentralized per-octet chains.
// 16 clusters x 8 CTAs x 512 threads. Rank r owns H-slice [32r,32r+32);
// cluster rows [8c,8c+8) (M=16 padded).
// Warp (joct = w&3, kg = w>>2): j-octet joct (8 j), k-quarter kg (64 k),
// nt = GATE -> each kg0 lane ends with all 4 gate partials for its (b, j-pair)
// in registers. Per-octet 4-way k-reduction via padded smem (stride 9 floats,
// SCALAR accesses only — float2 here faults on 4B-aligned odd offsets) +
// named barrier (128 threads). kg0 warp alone: reduce + gates + stage +
// __syncwarp + 8x 512B bulk copies with mbarrier complete_tx (expect
// 16 KB/step/parity). NO __syncthreads in the loop; 4 independent chains/CTA.
// ============================================================================

#define REC_THREADS 512
// byte offsets in dynamic smem
#define HB_B    0        // half [par 2][k 256][pl 2][b 16] = 32768 B
#define STG_B   32768    // half [par 2][oct 4][kin 8][pl 2][b 16] = 4096 B
#define CRED_B  36864    // float [oct 4][kg-1 3][lane 32][9] = 13824 B
#define MBAR_B  50688    // 2 x u64
#define SMEM_REC_BYTES 50720

__global__ void __cluster_dims__(8, 1, 1) __launch_bounds__(REC_THREADS, 1) lstm_rec_kernel(
    const float* __restrict__ fg_w_c, const float* __restrict__ fg_w_h,
    const float* __restrict__ ig_w_c, const float* __restrict__ ig_w_h,
    const float* __restrict__ in_w_h,
    const float* __restrict__ og_w_cn, const float* __restrict__ og_w_h,
    float* __restrict__ out)
{
    extern __shared__ char smc[];
    float* Cred = (float*)(smc + CRED_B);

    const int tid  = threadIdx.x;
    const int lane = tid & 31;
    const int w    = tid >> 5;         // 0..15
    const int joct = w & 3;            // j-octet
    const int kg   = w >> 2;           // k-quarter
    const int r    = blockIdx.x & 7;
    const int grp  = blockIdx.x >> 3;  // 0..15

    const uint32_t sbase = smem_u32_(smc);
    const uint32_t mb0 = sbase + MBAR_B;
    const uint32_t mb1 = mb0 + 8;

    // ---- Weight B-fragments in registers: [gate][kt][pair], hi + lo ----
    uint32_t bh[4][4][2], bl[4][4][2];
    {
        const float* Wg0[4] = { ig_w_h, fg_w_h, in_w_h, og_w_h };
        const int jrow = r * 32 + joct * 8 + (lane >> 2);
        #pragma unroll
        for (int g = 0; g < 4; g++) {
            const float* Wr = Wg0[g] + (size_t)jrow * 256;
            #pragma unroll
            for (int kt = 0; kt < 4; kt++) {
                const int kb = kg * 64 + kt * 16 + (lane & 3) * 2;
                split2_(*(const float2*)(Wr + kb),     bh[g][kt][0], bl[g][kt][0]);
                split2_(*(const float2*)(Wr + kb + 8), bh[g][kt][1], bl[g][kt][1]);
            }
        }
    }

    // Zero hbuf + stg (36864 B = 9216 words)
    for (int i = tid; i < 9216; i += REC_THREADS) ((uint32_t*)smc)[i] = 0u;

    if (tid == 0) {
        MBAR_INIT_(mb0, 1);
        MBAR_INIT_(mb1, 1);
        MBAR_ARRIVE_EXPECT_(mb0, 16384);
        MBAR_ARRIVE_EXPECT_(mb1, 16384);
    }

    // kg0-lane ownership: batch row b_own, j pair (j0, j0+1)
    const int b_own = lane >> 2;
    const int j0    = joct * 8 + (lane & 3) * 2;
    const int jg    = r * 32 + j0;
    const int bg    = grp * 8 + b_own;
    const float2 wcig = *(const float2*)&ig_w_c[jg];
    const float2 wcfg = *(const float2*)&fg_w_c[jg];
    const float2 wcog = *(const float2*)&og_w_cn[jg];
    const size_t rowoff = (size_t)bg * Nv * 256 + jg;

    __syncthreads();
    CLUSTER_SYNC_();   // zeroed buffers + mbarriers visible to all ranks

    float cm0 = 0.f, cm1 = 0.f, hn0 = 0.f, hn1 = 0.f;
    uint32_t ph0 = 0, ph1 = 0;

    const int krow_off = (lane & 7) + ((lane >> 4) << 3);
    const int bcol16   = ((lane >> 3) & 1) << 4;
    const int barid    = 1 + joct;

    #pragma unroll 1
    for (int n = 0; n < Nv; ++n) {
        const int q  = n & 1;
        const int qn = q ^ 1;

        if (n != 0) {
            const uint32_t mb = q ? mb1 : mb0;
            mbar_wait_(mb, q ? ph1 : ph0);
            if (q) ph1 ^= 1; else ph0 ^= 1;
            if (tid == 0) MBAR_ARRIVE_EXPECT_(mb, 16384);
        }

        // Gate-term loads (kg0 lanes): float2 over the j-pair; L2-prefetch next step.
        float2 pf, pi, pn_, po, pt1, pt2;
        if (kg == 0) {
            const size_t off = rowoff + (size_t)n * 256;
            pf  = *(const float2*)&g_pre[0][off];
            pi  = *(const float2*)&g_pre[1][off];
            pn_ = *(const float2*)&g_pre[2][off];
            po  = *(const float2*)&g_pre[3][off];
            pt1 = *(const float2*)&g_pre[4][off];
            pt2 = *(const float2*)&g_pre[5][off];
            if (n + 1 < Nv) {
                PREFETCH_L2_(&g_pre[0][off + 256]); PREFETCH_L2_(&g_pre[1][off + 256]);
                PREFETCH_L2_(&g_pre[2][off + 256]); PREFETCH_L2_(&g_pre[3][off + 256]);
                PREFETCH_L2_(&g_pre[4][off + 256]); PREFETCH_L2_(&g_pre[5][off + 256]);
            }
        }

        // ---- matmul: 4 kt x 4 gates x 3 passes = 48 mma, 8 ldsm ----
        float c[4][4];
        #pragma unroll
        for (int g = 0; g < 4; g++) { c[g][0]=0.f; c[g][1]=0.f; c[g][2]=0.f; c[g][3]=0.f; }
        #pragma unroll
        for (int kt = 0; kt < 4; kt++) {
            const uint32_t rowa = sbase + HB_B
                + (uint32_t)(q * 16384 + (kg * 64 + kt * 16 + krow_off) * 64 + bcol16);
            uint32_t ah[4], al[4];
            ldsm4t_(ah, rowa);        // hi plane
            ldsm4t_(al, rowa + 32);   // lo plane
            #pragma unroll
            for (int g = 0; g < 4; g++) {
                mma16816_(c[g], ah, bh[g][kt]);
                mma16816_(c[g], al, bh[g][kt]);
                mma16816_(c[g], ah, bl[g][kt]);
            }
        }

        // kg1-3 stash partials (padded stride 9 floats -> conflict-free; SCALAR only)
        if (kg != 0) {
            float* cr = Cred + ((joct * 3 + (kg - 1)) * 32 + lane) * 9;
            #pragma unroll
            for (int g = 0; g < 4; g++) {
                cr[g * 2]     = c[g][0];
                cr[g * 2 + 1] = c[g][1];
            }
        }
        BAR_SYNC_(barid, 128);

        if (kg == 0) {
            #pragma unroll
            for (int kc = 0; kc < 3; kc++) {
                const float* rr = Cred + ((joct * 3 + kc) * 32 + lane) * 9;
                #pragma unroll
                for (int g = 0; g < 4; g++) {
                    c[g][0] += rr[g * 2];
                    c[g][1] += rr[g * 2 + 1];
                }
            }

            // gates for j0 (index .x / c[g][0])
            {
                float ig  = sigmoidf_(wcig.x * cm0 + c[0][0] + pi.x);
                float fg  = sigmoidf_(wcfg.x * cm0 + c[1][0] + pf.x);
                float inn = tanh_fast_(c[2][0] + pn_.x);
                float fc  = fg * cm0;
                float gi  = ig * inn;
                float cmh = fc + gi * pt1.x;
                cm0       = fc + gi * pt2.x;
                float og  = sigmoidf_(wcog.x * cmh + c[3][0] + po.x);
                hn0       = og * tanh_fast_(cmh);
            }
            // gates for j0+1 (index .y / c[g][1])
            {
                float ig  = sigmoidf_(wcig.y * cm1 + c[0][1] + pi.y);
                float fg  = sigmoidf_(wcfg.y * cm1 + c[1][1] + pf.y);
                float inn = tanh_fast_(c[2][1] + pn_.y);
                float fc  = fg * cm1;
                float gi  = ig * inn;
                float cmh = fc + gi * pt1.y;
                cm1       = fc + gi * pt2.y;
                float og  = sigmoidf_(wcog.y * cmh + c[3][1] + po.y);
                hn1       = og * tanh_fast_(cmh);
            }

            if (n < Nv - 1) {
                // stage [par][oct][kin 8][pl 2][b 16]
                __half* S = (__half*)(smc + STG_B)
                          + (qn * 4 + joct) * 256 + ((lane & 3) * 2) * 32 + b_own;
                __half h0 = __float2half_rn(hn0);
                S[0]  = h0;
                S[16] = __float2half_rn(hn0 - __half2float(h0));
                __half h1 = __float2half_rn(hn1);
                S[32] = h1;
                S[48] = __float2half_rn(hn1 - __half2float(h1));
                __syncwarp();
                if (lane < 8) {
                    FENCE_ASYNC_();
                    bulk_copy_rank_(
                        sbase + HB_B  + (uint32_t)(qn * 16384 + (r * 32 + joct * 8) * 64),
                        sbase + STG_B + (uint32_t)((qn * 4 + joct) * 512),
                        qn ? mb1 : mb0, (uint32_t)lane, 512);
                }
            }
        }
    }

    CLUSTER_SYNC_();   // keep cluster resident until all copies consumed

    if (kg == 0) {
        out[(size_t)bg * 256 + jg]             = hn0;
        out[(size_t)bg * 256 + jg + 1]         = hn1;
        out[32768 + (size_t)bg * 256 + jg]     = cm0;
        out[32768 + (size_t)bg * 256 + jg + 1] = cm1;
    }
}

// ============================================================================
// Launch
// ============================================================================
extern "C" void kernel_launch(void* const* d_in, const int* in_sizes, int n_in,
                              void* d_out, int out_size)
{
    const float* x       = (const float*)d_in[0];
    const float* t       = (const float*)d_in[1];
    const float* fg_w_c  = (const float*)d_in[2];
    const float* fg_w_h  = (const float*)d_in[3];
    const float* fg_w_x  = (const float*)d_in[4];
    const float* fg_b    = (const float*)d_in[5];
    const float* ig_w_c  = (const float*)d_in[6];
    const float* ig_w_h  = (const float*)d_in[7];
    const float* ig_w_x  = (const float*)d_in[8];
    const float* ig_b    = (const float*)d_in[9];
    const float* in_w_h  = (const float*)d_in[10];
    const float* in_w_x  = (const float*)d_in[11];
    const float* in_b    = (const float*)d_in[12];
    const float* og_w_cn = (const float*)d_in[13];
    const float* og_w_h  = (const float*)d_in[14];
    const float* og_w_x  = (const float*)d_in[15];
    const float* og_b    = (const float*)d_in[16];
    const float* og_w_t  = (const float*)d_in[17];
    const float* tg1_w_x = (const float*)d_in[18];
    const float* tg1_w_t = (const float*)d_in[19];
    const float* tg1_b   = (const float*)d_in[20];
    const float* tg2_w_x = (const float*)d_in[21];
    const float* tg2_w_t = (const float*)d_in[22];
    const float* tg2_b   = (const float*)d_in[23];
    float* out = (float*)d_out;

    cudaFuncSetAttribute(precompute_kernel, cudaFuncAttributeMaxDynamicSharedMemorySize, PRE_SMEM_BYTES);
    cudaFuncSetAttribute(lstm_rec_kernel,   cudaFuncAttributeMaxDynamicSharedMemorySize, SMEM_REC_BYTES);

    dim3 gp(512, 24);
    precompute_kernel<<<gp, 256, PRE_SMEM_BYTES>>>(
        x, t,
        fg_w_x, fg_b, ig_w_x, ig_b, in_w_x, in_b,
        og_w_x, og_b, og_w_t,
        tg1_w_x, tg1_b, tg1_w_t,
        tg2_w_x, tg2_b, tg2_w_t);

    lstm_rec_kernel<<<128, REC_THREADS, SMEM_REC_BYTES>>>(
        fg_w_c, fg_w_h, ig_w_c, ig_w_h, in_w_h, og_w_cn, og_w_h, out);
}

// round 13
// speedup vs baseline: 1.1918x; 1.1918x over previous
#include <cuda_runtime.h>
#include <cuda_fp16.h>
#include <cstdint>

#define Bv 128
#define Nv 512
#define Xv 128
#define Hv 256
#define BN (Bv*Nv)           // 65536
#define GSZ (BN*Hv)          // 16777216 floats per gate buffer

// 6 precomputed gate-input buffers: 0=fg_x 1=ig_x 2=in_x 3=og_x 4=tm1 5=tm2
__device__ float g_pre[6][GSZ];

__device__ __forceinline__ float sigmoidf_(float v) { return 1.0f / (1.0f + __expf(-v)); }

// exp-based tanh: ~5 instr, rel err ~1e-6. Args bounded, no overflow path.
__device__ __forceinline__ float tanh_fast_(float x) {
    float e = __expf(-2.0f * x);
    return __fdividef(1.0f - e, 1.0f + e);
}

__device__ __forceinline__ uint32_t smem_u32_(const void* p) {
    uint32_t a;
    asm("{ .reg .u64 t; cvta.to.shared.u64 t, %1; cvt.u32.u64 %0, t; }" : "=r"(a) : "l"(p));
    return a;
}

// ---- f32x2 packed-math helpers (precompute kernel) ----
__device__ __forceinline__ unsigned long long pack2_(float a) {
    unsigned long long r;
    asm("mov.b64 %0, {%1, %1};" : "=l"(r) : "f"(a));
    return r;
}
__device__ __forceinline__ void ffma2_(unsigned long long& d, unsigned long long a, unsigned long long b) {
    asm("fma.rn.f32x2 %0, %1, %2, %0;" : "+l"(d) : "l"(a), "l"(b));
}
__device__ __forceinline__ float2 unpack2_(unsigned long long v) {
    float lo, hi;
    asm("mov.b64 {%0, %1}, %2;" : "=f"(lo), "=f"(hi) : "l"(v));
    return make_float2(lo, hi);
}

// ---- tensor-core helpers (rec kernel) ----
__device__ __forceinline__ void ldsm4t_(uint32_t* d, uint32_t addr) {
    asm volatile("ldmatrix.sync.aligned.m8n8.x4.trans.shared.b16 {%0,%1,%2,%3}, [%4];"
        : "=r"(d[0]), "=r"(d[1]), "=r"(d[2]), "=r"(d[3]) : "r"(addr));
}
__device__ __forceinline__ void mma16816_(float* c, const uint32_t* a, const uint32_t* b) {
    asm volatile(
        "mma.sync.aligned.m16n8k16.row.col.f32.f16.f16.f32 "
        "{%0,%1,%2,%3}, {%4,%5,%6,%7}, {%8,%9}, {%0,%1,%2,%3};"
        : "+f"(c[0]), "+f"(c[1]), "+f"(c[2]), "+f"(c[3])
        : "r"(a[0]), "r"(a[1]), "r"(a[2]), "r"(a[3]), "r"(b[0]), "r"(b[1]));
}
// Split fp32 pair into hi-fp16x2 and lo-residual-fp16x2.
__device__ __forceinline__ void split2_(float2 v, uint32_t& hi, uint32_t& lo) {
    __half h0 = __float2half_rn(v.x), h1 = __float2half_rn(v.y);
    float r0 = v.x - __half2float(h0), r1 = v.y - __half2float(h1);
    __half2 H = __halves2half2(h0, h1);
    __half2 L = __floats2half2_rn(r0, r1);
    hi = *(uint32_t*)&H;
    lo = *(uint32_t*)&L;
}

// Bulk DSMEM copy: local smem src -> rank rk's smem dst (same-offset address
// space), crediting rank rk's mbarrier with complete_tx bytes.
__device__ __forceinline__ void bulk_copy_rank_(uint32_t dst, uint32_t src,
                                                uint32_t mb, uint32_t rank,
                                                uint32_t bytes) {
    asm volatile(
        "{\n\t"
        ".reg .b32 rd, rm;\n\t"
        "mapa.shared::cluster.u32 rd, %0, %3;\n\t"
        "mapa.shared::cluster.u32 rm, %2, %3;\n\t"
        "cp.async.bulk.shared::cluster.shared::cta.mbarrier::complete_tx::bytes [rd], [%1], %4, [rm];\n\t"
        "}"
        :: "r"(dst), "r"(src), "r"(mb), "r"(rank), "r"(bytes) : "memory");
}

#define MBAR_INIT_(a, c) \
    asm volatile("mbarrier.init.shared.b64 [%0], %1;" :: "r"(a), "r"(c) : "memory")

#define MBAR_ARRIVE_EXPECT_(a, bytes) \
    asm volatile("mbarrier.arrive.expect_tx.shared.b64 _, [%0], %1;" \
                 :: "r"(a), "r"(bytes) : "memory")

#define FENCE_ASYNC_() asm volatile("fence.proxy.async.shared::cta;" ::: "memory")

__device__ __forceinline__ void mbar_wait_(uint32_t a, uint32_t parity) {
    asm volatile(
        "{\n\t"
        ".reg .pred P;\n\t"
        "WL_%=:\n\t"
        "mbarrier.try_wait.parity.acquire.cta.shared::cta.b64 P, [%0], %1, 0x989680;\n\t"
        "@P bra.uni WD_%=;\n\t"
        "bra.uni WL_%=;\n\t"
        "WD_%=:\n\t"
        "}"
        :: "r"(a), "r"(parity) : "memory");
}

#define CLUSTER_SYNC_() do { \
    asm volatile("barrier.cluster.arrive.aligned;" ::: "memory"); \
    asm volatile("barrier.cluster.wait.aligned;"   ::: "memory"); \
} while (0)

#define BAR_SYNC_(id, cnt) \
    asm volatile("bar.sync %0, %1;" :: "r"(id), "r"(cnt) : "memory")

// ============================================================================
// Phase 1: precompute all input-dependent gate terms. (unchanged)
// grid (512 bn-tiles, 24 h-tiles of 64), block 256, 2 CTAs/SM.
// ============================================================================

#define XS_STRIDE 132
#define WS_STRIDE 68
#define PRE_SMEM_BYTES ((128 * XS_STRIDE + 128 * WS_STRIDE) * 4)   // 102400

__global__ void __launch_bounds__(256, 2) precompute_kernel(
    const float* __restrict__ x, const float* __restrict__ tvec,
    const float* __restrict__ fg_w_x, const float* __restrict__ fg_b,
    const float* __restrict__ ig_w_x, const float* __restrict__ ig_b,
    const float* __restrict__ in_w_x, const float* __restrict__ in_b,
    const float* __restrict__ og_w_x, const float* __restrict__ og_b, const float* __restrict__ og_w_t,
    const float* __restrict__ tg1_w_x, const float* __restrict__ tg1_b, const float* __restrict__ tg1_w_t,
    const float* __restrict__ tg2_w_x, const float* __restrict__ tg2_b, const float* __restrict__ tg2_w_t)
{
    extern __shared__ float sm[];
    float* xs = sm;                        // [128][132]
    float* ws = sm + 128 * XS_STRIDE;      // [128 k][68]

    const int tid  = threadIdx.x;
    const int bn0  = blockIdx.x * 128;
    const int ht   = blockIdx.y;
    const int gate = ht >> 2;
    const int hl0  = (ht & 3) * 64;

    const float* wptr; const float* bptr; const float* tptr = nullptr;
    switch (gate) {
        case 0:  wptr = fg_w_x;  bptr = fg_b;  break;
        case 1:  wptr = ig_w_x;  bptr = ig_b;  break;
        case 2:  wptr = in_w_x;  bptr = in_b;  break;
        case 3:  wptr = og_w_x;  bptr = og_b;  tptr = og_w_t;  break;
        case 4:  wptr = tg1_w_x; bptr = tg1_b; tptr = tg1_w_t; break;
        default: wptr = tg2_w_x; bptr = tg2_b; tptr = tg2_w_t; break;
    }

    for (int i = tid; i < 4096; i += 256) {
        int row = i >> 5, kq = i & 31;
        *(float4*)(xs + row * XS_STRIDE + kq * 4) =
            *(const float4*)(x + (size_t)(bn0 + row) * 128 + kq * 4);
    }
    for (int i = tid; i < 2048; i += 256) {
        int h = i >> 5, kq = i & 31;
        float4 v = *(const float4*)(wptr + (size_t)(hl0 + h) * 128 + kq * 4);
        ws[(kq * 4 + 0) * WS_STRIDE + h] = v.x;
        ws[(kq * 4 + 1) * WS_STRIDE + h] = v.y;
        ws[(kq * 4 + 2) * WS_STRIDE + h] = v.z;
        ws[(kq * 4 + 3) * WS_STRIDE + h] = v.w;
    }
    __syncthreads();

    const int trow = tid >> 3;   // 0..31
    const int tcol = tid & 7;    // 0..7

    unsigned long long acc2[4][4];
    #pragma unroll
    for (int i = 0; i < 4; i++) {
        #pragma unroll
        for (int q = 0; q < 4; q++) acc2[i][q] = 0ull;
    }

    #pragma unroll 2
    for (int k4 = 0; k4 < 32; ++k4) {
        float4 av[4];
        #pragma unroll
        for (int i = 0; i < 4; i++)
            av[i] = *(const float4*)(xs + (trow * 4 + i) * XS_STRIDE + k4 * 4);
        #pragma unroll
        for (int cc = 0; cc < 4; cc++) {
            const float* wr = ws + (k4 * 4 + cc) * WS_STRIDE + tcol * 8;
            ulonglong2 b01 = *(const ulonglong2*)(wr);
            ulonglong2 b23 = *(const ulonglong2*)(wr + 4);
            #pragma unroll
            for (int i = 0; i < 4; i++) {
                float a = (cc == 0) ? av[i].x : (cc == 1) ? av[i].y
                        : (cc == 2) ? av[i].z : av[i].w;
                unsigned long long aa = pack2_(a);
                ffma2_(acc2[i][0], aa, b01.x);
                ffma2_(acc2[i][1], aa, b01.y);
                ffma2_(acc2[i][2], aa, b23.x);
                ffma2_(acc2[i][3], aa, b23.y);
            }
        }
    }

    const int hgbase = hl0 + tcol * 8;
    float bias[8], tw[8];
    #pragma unroll
    for (int jj = 0; jj < 8; jj++) {
        bias[jj] = bptr[hgbase + jj];
        tw[jj]   = (tptr != nullptr) ? tptr[hgbase + jj] : 0.0f;
    }
    float* outg = &g_pre[gate][0];
    #pragma unroll
    for (int i = 0; i < 4; i++) {
        int row = bn0 + trow * 4 + i;
        float tv = (gate >= 3) ? tvec[row] : 0.0f;
        float oo[8];
        #pragma unroll
        for (int q = 0; q < 4; q++) {
            float2 u = unpack2_(acc2[i][q]);
            oo[2 * q]     = u.x;
            oo[2 * q + 1] = u.y;
        }
        float o[8];
        #pragma unroll
        for (int jj = 0; jj < 8; jj++) {
            float v;
            if (gate < 3)       v = oo[jj] + bias[jj];
            else if (gate == 3) v = oo[jj] + tw[jj] * tv + bias[jj];
            else                v = sigmoidf_(oo[jj] + tanhf(tw[jj] * tv) + bias[jj]);
            o[jj] = v;
        }
        float4* dst = (float4*)(outg + (size_t)row * 256 + hgbase);
        dst[0] = make_float4(o[0], o[1], o[2], o[3]);
        dst[1] = make_float4(o[4], o[5], o[6], o[7]);
    }
}

// ============================================================================
// Phase 2: recurrence via tensor cores (exact R8 structure, 2080us best) plus
// ONE change: gate-term (g_pre) loads are software-pipelined ONE FULL STEP
// ahead in registers. The loads for step n+1 are issued right after step n's
// wait and consumed a whole step (~7K cyc) later -> DRAM latency AND its
// per-SM jitter (amplified by the 8-SM lock-step max) leave the chain.
// 16 clusters x 8 CTAs x 512 threads; M=16 HMMA; hi+lo fp16 split planes;
// 16x 1KB bulk copies + mbarrier complete_tx per step.
// ============================================================================

#define REC_THREADS 512
// byte offsets in dynamic smem
#define HBUF_B   0        // half [par 2][plane 2][k 256][b 16] = 32768 B
#define STG_B    32768    // half [par 2][plane 2][j 32][b 16] = 4096 B
#define CRED_B   36864    // float [kg 4][b 8][136] = 17408 B
#define MBAR_B   54272    // 2 x u64
#define SMEM_REC_BYTES 54400

__global__ void __cluster_dims__(8, 1, 1) __launch_bounds__(REC_THREADS, 1) lstm_rec_kernel(
    const float* __restrict__ fg_w_c, const float* __restrict__ fg_w_h,
    const float* __restrict__ ig_w_c, const float* __restrict__ ig_w_h,
    const float* __restrict__ in_w_h,
    const float* __restrict__ og_w_cn, const float* __restrict__ og_w_h,
    float* __restrict__ out)
{
    extern __shared__ char smc[];
    __half* Sg   = (__half*)(smc + STG_B);
    float*  Cred = (float*)(smc + CRED_B);

    const int tid  = threadIdx.x;
    const int lane = tid & 31;
    const int w    = tid >> 5;         // 0..15
    const int r    = blockIdx.x & 7;
    const int grp  = blockIdx.x >> 3;
    const int ns   = w & 3;            // n-slice (32 cols)
    const int kg   = w >> 2;           // k-group (64 k)

    const uint32_t sbase = smem_u32_(smc);
    const uint32_t mb0 = sbase + MBAR_B;
    const uint32_t mb1 = mb0 + 8;

    // ---- Load weight B-fragments into registers (hi + lo split) ----
    uint32_t bh[4][4][2], bl[4][4][2];   // [nt][kt][pair]
    {
        const float* Wg0[4] = { ig_w_h, fg_w_h, in_w_h, og_w_h };
        #pragma unroll
        for (int nt = 0; nt < 4; nt++) {
            const int n  = ns * 32 + nt * 8 + (lane >> 2);
            const float* Wr = Wg0[n >> 5] + (size_t)(r * 32 + (n & 31)) * 256;
            #pragma unroll
            for (int kt = 0; kt < 4; kt++) {
                const int kb = kg * 64 + kt * 16 + (lane & 3) * 2;
                float2 v0 = *(const float2*)(Wr + kb);
                float2 v1 = *(const float2*)(Wr + kb + 8);
                split2_(v0, bh[nt][kt][0], bl[nt][kt][0]);
                split2_(v1, bh[nt][kt][1], bl[nt][kt][1]);
            }
        }
    }

    // Zero h buffers + staging (36864 B = 9216 words)
    for (int i = tid; i < 9216; i += REC_THREADS) ((uint32_t*)smc)[i] = 0u;

    if (tid == 0) {
        MBAR_INIT_(mb0, 1);
        MBAR_INIT_(mb1, 1);
        MBAR_ARRIVE_EXPECT_(mb0, 16384);
        MBAR_ARRIVE_EXPECT_(mb1, 16384);
    }

    // Owner-thread data (threads 0-255): b = tid>>5, j = lane
    const int b_own = w;               // valid when tid < 256
    const int j_own = lane;
    const int jg    = r * 32 + j_own;
    const int bg    = grp * 8 + b_own;
    const float wc_ig = ig_w_c[jg];
    const float wc_fg = fg_w_c[jg];
    const float wc_og = og_w_cn[jg];
    const size_t rowoff = (size_t)bg * Nv * 256 + jg;

    __syncthreads();
    CLUSTER_SYNC_();   // zeroed buffers + mbarriers visible to all ranks

    float cmv = 0.0f, hnv = 0.0f;
    uint32_t ph0 = 0, ph1 = 0;

    // Gate-term pipeline registers: p_cur = step n terms, loaded one step early.
    float p0 = 0.f, p1 = 0.f, p2 = 0.f, p3 = 0.f, p4 = 0.f, p5 = 0.f;
    if (tid < 256) {
        p0 = __ldcs(&g_pre[0][rowoff]);
        p1 = __ldcs(&g_pre[1][rowoff]);
        p2 = __ldcs(&g_pre[2][rowoff]);
        p3 = __ldcs(&g_pre[3][rowoff]);
        p4 = __ldcs(&g_pre[4][rowoff]);
        p5 = __ldcs(&g_pre[5][rowoff]);
    }

    // ldmatrix per-lane addressing (k-major Ht[k][b], row = 32 B):
    const int krow_off = (lane & 7) + ((lane >> 4) << 3);
    const int bcol     = ((lane >> 3) & 1) << 3;

    #pragma unroll 1
    for (int n = 0; n < Nv; ++n) {
        const int q = n & 1;

        if (n != 0) {
            const uint32_t mb = q ? mb1 : mb0;
            mbar_wait_(mb, q ? ph1 : ph0);
            if (q) ph1 ^= 1; else ph0 ^= 1;
            if (tid == 0) MBAR_ARRIVE_EXPECT_(mb, 16384);
        }

        // Issue NEXT step's gate-term loads now; consumed next iteration.
        float q0 = 0.f, q1 = 0.f, q2 = 0.f, q3 = 0.f, q4 = 0.f, q5 = 0.f;
        if (tid < 256 && n + 1 < Nv) {
            const size_t off = rowoff + (size_t)(n + 1) * 256;
            q0 = __ldcs(&g_pre[0][off]); q1 = __ldcs(&g_pre[1][off]);
            q2 = __ldcs(&g_pre[2][off]); q3 = __ldcs(&g_pre[3][off]);
            q4 = __ldcs(&g_pre[4][off]); q5 = __ldcs(&g_pre[5][off]);
        }

        // ---- Tensor-core matmul: 4 k-tiles x 4 n-tiles x 3 passes ----
        float c[4][4];
        #pragma unroll
        for (int nt = 0; nt < 4; nt++) { c[nt][0] = 0.f; c[nt][1] = 0.f; c[nt][2] = 0.f; c[nt][3] = 0.f; }

        #pragma unroll
        for (int kt = 0; kt < 4; kt++) {
            const uint32_t hbase = (uint32_t)(q * 8192 + (kg * 64 + kt * 16 + krow_off) * 16 + bcol);
            uint32_t ah[4], al[4];
            ldsm4t_(ah, sbase + HBUF_B + 2u * hbase);            // hi plane
            ldsm4t_(al, sbase + HBUF_B + 2u * (hbase + 4096));   // lo plane
            #pragma unroll
            for (int nt = 0; nt < 4; nt++) {
                mma16816_(c[nt], ah, bh[nt][kt]);
                mma16816_(c[nt], al, bh[nt][kt]);
                mma16816_(c[nt], ah, bl[nt][kt]);
            }
        }

        // Partials to SMEM (rows 0-7 only: c0,c1)
        {
            const int bq = lane >> 2;
            #pragma unroll
            for (int nt = 0; nt < 4; nt++) {
                const int n0 = ns * 32 + nt * 8 + (lane & 3) * 2;
                *(float2*)&Cred[(kg * 8 + bq) * 136 + n0] = make_float2(c[nt][0], c[nt][1]);
            }
        }
        __syncthreads();

        if (tid < 256) {
            // 4-way k-reduction: gate order n = [ig | fg | in | og]
            float s_ig = 0.f, s_fg = 0.f, s_in = 0.f, s_og = 0.f;
            #pragma unroll
            for (int kc = 0; kc < 4; kc++) {
                const float* rr = Cred + (kc * 8 + b_own) * 136 + j_own;
                s_ig += rr[0];
                s_fg += rr[32];
                s_in += rr[64];
                s_og += rr[96];
            }

            float ig  = sigmoidf_(wc_ig * cmv + s_ig + p1);
            float fg  = sigmoidf_(wc_fg * cmv + s_fg + p0);
            float inn = tanh_fast_(s_in + p2);
            float fc  = fg * cmv;
            float gi  = ig * inn;
            float cmh = fc + gi * p4;
            cmv       = fc + gi * p5;
            float og  = sigmoidf_(wc_og * cmh + s_og + p3);
            hnv       = og * tanh_fast_(cmh);

            if (n < Nv - 1) {
                const int qn = q ^ 1;
                __half hh = __float2half_rn(hnv);
                __half hl = __float2half_rn(hnv - __half2float(hh));
                Sg[qn * 1024 + 0 * 512 + j_own * 16 + b_own] = hh;
                Sg[qn * 1024 + 1 * 512 + j_own * 16 + b_own] = hl;
                BAR_SYNC_(1, 256);
                if (tid < 16) {
                    const uint32_t rk = (uint32_t)(tid & 7);
                    const uint32_t pl = (uint32_t)(tid >> 3);
                    FENCE_ASYNC_();
                    bulk_copy_rank_(
                        sbase + HBUF_B + 2u * (uint32_t)(qn * 8192 + pl * 4096 + (r * 32) * 16),
                        sbase + STG_B  + 2u * (uint32_t)(qn * 1024 + pl * 512),
                        qn ? mb1 : mb0, rk, 1024);
                }
            }
            // rotate the gate-term pipeline
            p0 = q0; p1 = q1; p2 = q2; p3 = q3; p4 = q4; p5 = q5;
        }
    }

    CLUSTER_SYNC_();   // keep cluster resident until all copies consumed

    if (tid < 256) {
        out[(size_t)bg * 256 + jg]         = hnv;
        out[32768 + (size_t)bg * 256 + jg] = cmv;
    }
}

// ============================================================================
// Launch
// ============================================================================
extern "C" void kernel_launch(void* const* d_in, const int* in_sizes, int n_in,
                              void* d_out, int out_size)
{
    const float* x       = (const float*)d_in[0];
    const float* t       = (const float*)d_in[1];
    const float* fg_w_c  = (const float*)d_in[2];
    const float* fg_w_h  = (const float*)d_in[3];
    const float* fg_w_x  = (const float*)d_in[4];
    const float* fg_b    = (const float*)d_in[5];
    const float* ig_w_c  = (const float*)d_in[6];
    const float* ig_w_h  = (const float*)d_in[7];
    const float* ig_w_x  = (const float*)d_in[8];
    const float* ig_b    = (const float*)d_in[9];
    const float* in_w_h  = (const float*)d_in[10];
    const float* in_w_x  = (const float*)d_in[11];
    const float* in_b    = (const float*)d_in[12];
    const float* og_w_cn = (const float*)d_in[13];
    const float* og_w_h  = (const float*)d_in[14];
    const float* og_w_x  = (const float*)d_in[15];
    const float* og_b    = (const float*)d_in[16];
    const float* og_w_t  = (const float*)d_in[17];
    const float* tg1_w_x = (const float*)d_in[18];
    const float* tg1_w_t = (const float*)d_in[19];
    const float* tg1_b   = (const float*)d_in[20];
    const float* tg2_w_x = (const float*)d_in[21];
    const float* tg2_w_t = (const float*)d_in[22];
    const float* tg2_b   = (const float*)d_in[23];
    float* out = (float*)d_out;

    cudaFuncSetAttribute(precompute_kernel, cudaFuncAttributeMaxDynamicSharedMemorySize, PRE_SMEM_BYTES);
    cudaFuncSetAttribute(lstm_rec_kernel,   cudaFuncAttributeMaxDynamicSharedMemorySize, SMEM_REC_BYTES);

    dim3 gp(512, 24);
    precompute_kernel<<<gp, 256, PRE_SMEM_BYTES>>>(
        x, t,
        fg_w_x, fg_b, ig_w_x, ig_b, in_w_x, in_b,
        og_w_x, og_b, og_w_t,
        tg1_w_x, tg1_b, tg1_w_t,
        tg2_w_x, tg2_b, tg2_w_t);

    lstm_rec_kernel<<<128, REC_THREADS, SMEM_REC_BYTES>>>(
        fg_w_c, fg_w_h, ig_w_c, ig_w_h, in_w_h, og_w_cn, og_w_h, out);
}

// round 14
// speedup vs baseline: 1.2156x; 1.0199x over previous
#include <cuda_runtime.h>
#include <cuda_fp16.h>
#include <cstdint>

#define Bv 128
#define Nv 512
#define Xv 128
#define Hv 256
#define BN (Bv*Nv)           // 65536
#define GSZ (BN*Hv)          // 16777216 floats per gate buffer

// 6 precomputed gate-input buffers: 0=fg_x 1=ig_x 2=in_x 3=og_x 4=tm1 5=tm2
__device__ float g_pre[6][GSZ];

__device__ __forceinline__ float sigmoidf_(float v) { return 1.0f / (1.0f + __expf(-v)); }

// exp-based tanh: ~5 instr, rel err ~1e-6. Args bounded, no overflow path.
__device__ __forceinline__ float tanh_fast_(float x) {
    float e = __expf(-2.0f * x);
    return __fdividef(1.0f - e, 1.0f + e);
}

__device__ __forceinline__ uint32_t smem_u32_(const void* p) {
    uint32_t a;
    asm("{ .reg .u64 t; cvta.to.shared.u64 t, %1; cvt.u32.u64 %0, t; }" : "=r"(a) : "l"(p));
    return a;
}

// ---- tensor-core helpers ----
__device__ __forceinline__ void ldsm4t_(uint32_t* d, uint32_t addr) {
    asm volatile("ldmatrix.sync.aligned.m8n8.x4.trans.shared.b16 {%0,%1,%2,%3}, [%4];"
        : "=r"(d[0]), "=r"(d[1]), "=r"(d[2]), "=r"(d[3]) : "r"(addr));
}
__device__ __forceinline__ void mma16816_(float* c, const uint32_t* a, const uint32_t* b) {
    asm volatile(
        "mma.sync.aligned.m16n8k16.row.col.f32.f16.f16.f32 "
        "{%0,%1,%2,%3}, {%4,%5,%6,%7}, {%8,%9}, {%0,%1,%2,%3};"
        : "+f"(c[0]), "+f"(c[1]), "+f"(c[2]), "+f"(c[3])
        : "r"(a[0]), "r"(a[1]), "r"(a[2]), "r"(a[3]), "r"(b[0]), "r"(b[1]));
}
// Split fp32 pair into hi-fp16x2 and lo-residual-fp16x2.
__device__ __forceinline__ void split2_(float2 v, uint32_t& hi, uint32_t& lo) {
    __half h0 = __float2half_rn(v.x), h1 = __float2half_rn(v.y);
    float r0 = v.x - __half2float(h0), r1 = v.y - __half2float(h1);
    __half2 H = __halves2half2(h0, h1);
    __half2 L = __floats2half2_rn(r0, r1);
    hi = *(uint32_t*)&H;
    lo = *(uint32_t*)&L;
}

// Bulk DSMEM copy: local smem src -> rank rk's smem dst (same-offset address
// space), crediting rank rk's mbarrier with complete_tx bytes.
__device__ __forceinline__ void bulk_copy_rank_(uint32_t dst, uint32_t src,
                                                uint32_t mb, uint32_t rank,
                                                uint32_t bytes) {
    asm volatile(
        "{\n\t"
        ".reg .b32 rd, rm;\n\t"
        "mapa.shared::cluster.u32 rd, %0, %3;\n\t"
        "mapa.shared::cluster.u32 rm, %2, %3;\n\t"
        "cp.async.bulk.shared::cluster.shared::cta.mbarrier::complete_tx::bytes [rd], [%1], %4, [rm];\n\t"
        "}"
        :: "r"(dst), "r"(src), "r"(mb), "r"(rank), "r"(bytes) : "memory");
}

#define MBAR_INIT_(a, c) \
    asm volatile("mbarrier.init.shared.b64 [%0], %1;" :: "r"(a), "r"(c) : "memory")

#define MBAR_ARRIVE_EXPECT_(a, bytes) \
    asm volatile("mbarrier.arrive.expect_tx.shared.b64 _, [%0], %1;" \
                 :: "r"(a), "r"(bytes) : "memory")

#define FENCE_ASYNC_() asm volatile("fence.proxy.async.shared::cta;" ::: "memory")

__device__ __forceinline__ void mbar_wait_(uint32_t a, uint32_t parity) {
    asm volatile(
        "{\n\t"
        ".reg .pred P;\n\t"
        "WL_%=:\n\t"
        "mbarrier.try_wait.parity.acquire.cta.shared::cta.b64 P, [%0], %1, 0x989680;\n\t"
        "@P bra.uni WD_%=;\n\t"
        "bra.uni WL_%=;\n\t"
        "WD_%=:\n\t"
        "}"
        :: "r"(a), "r"(parity) : "memory");
}

#define CLUSTER_SYNC_() do { \
    asm volatile("barrier.cluster.arrive.aligned;" ::: "memory"); \
    asm volatile("barrier.cluster.wait.aligned;"   ::: "memory"); \
} while (0)

#define BAR_SYNC_(id, cnt) \
    asm volatile("bar.sync %0, %1;" :: "r"(id), "r"(cnt) : "memory")

// ============================================================================
// Phase 1: precompute via TENSOR CORES (split-fp16, 3-pass, same machinery as
// the rec kernel). grid (512 bn-tiles, 24 ht), block 256, 2 CTAs/SM.
// Block: 128 bn x 64 h of one gate-matrix. x tile converted once to k-major
// hi/lo fp16 planes [k 128][m 136] (stride 136 halves -> conflict-free
// ldmatrix.trans, layout proven in rec kernel). W B-fragments in registers
// (split2_ path, also proven). Warp (wm = w&1, wn = w>>2? no: wn = w>>1):
// 64 m x 16 n x K=128, 192 mma in two m-halves. Epilogue: bias/t/activation
// on C-frags, float2 stores direct to g_pre.
// ============================================================================

#define XP_STRIDE 136
#define PLANE_HALVES (128 * XP_STRIDE)          // 17408 halves
#define PC_SMEM_BYTES (2 * PLANE_HALVES * 2)    // 69632 B

__global__ void __launch_bounds__(256, 2) precompute_kernel(
    const float* __restrict__ x, const float* __restrict__ tvec,
    const float* __restrict__ fg_w_x, const float* __restrict__ fg_b,
    const float* __restrict__ ig_w_x, const float* __restrict__ ig_b,
    const float* __restrict__ in_w_x, const float* __restrict__ in_b,
    const float* __restrict__ og_w_x, const float* __restrict__ og_b, const float* __restrict__ og_w_t,
    const float* __restrict__ tg1_w_x, const float* __restrict__ tg1_b, const float* __restrict__ tg1_w_t,
    const float* __restrict__ tg2_w_x, const float* __restrict__ tg2_b, const float* __restrict__ tg2_w_t)
{
    extern __shared__ __half xp[];   // [plane 2][k 128][m 136]

    const int tid  = threadIdx.x;
    const int lane = tid & 31;
    const int w    = tid >> 5;       // 0..7
    const int bn0  = blockIdx.x * 128;
    const int ht   = blockIdx.y;
    const int gate = ht >> 2;
    const int hl0  = (ht & 3) * 64;

    const float* wptr; const float* bptr; const float* tptr = nullptr;
    switch (gate) {
        case 0:  wptr = fg_w_x;  bptr = fg_b;  break;
        case 1:  wptr = ig_w_x;  bptr = ig_b;  break;
        case 2:  wptr = in_w_x;  bptr = in_b;  break;
        case 3:  wptr = og_w_x;  bptr = og_b;  tptr = og_w_t;  break;
        case 4:  wptr = tg1_w_x; bptr = tg1_b; tptr = tg1_w_t; break;
        default: wptr = tg2_w_x; bptr = tg2_b; tptr = tg2_w_t; break;
    }

    // Convert x tile [128 m][128 k] fp32 -> k-major hi/lo planes xp[pl][k][m].
    for (int i = tid; i < 4096; i += 256) {
        const int m  = i >> 5;
        const int kq = i & 31;
        float4 v = *(const float4*)(x + (size_t)(bn0 + m) * 128 + kq * 4);
        const float vv[4] = { v.x, v.y, v.z, v.w };
        #pragma unroll
        for (int s = 0; s < 4; s++) {
            const int k = kq * 4 + s;
            __half hh = __float2half_rn(vv[s]);
            xp[k * XP_STRIDE + m]                = hh;
            xp[PLANE_HALVES + k * XP_STRIDE + m] = __float2half_rn(vv[s] - __half2float(hh));
        }
    }

    // W B-fragments in registers: [nt 2][kt 8][pair 2], hi + lo.
    const int wm = w & 1;    // m half (64 rows)
    const int wn = w >> 1;   // n quarter (16 cols)
    uint32_t bh[2][8][2], bl[2][8][2];
    {
        #pragma unroll
        for (int nt = 0; nt < 2; nt++) {
            const int n = hl0 + wn * 16 + nt * 8 + (lane >> 2);
            const float* Wr = wptr + (size_t)n * 128;
            #pragma unroll
            for (int kt = 0; kt < 8; kt++) {
                const int kb = kt * 16 + (lane & 3) * 2;
                split2_(*(const float2*)(Wr + kb),     bh[nt][kt][0], bl[nt][kt][0]);
                split2_(*(const float2*)(Wr + kb + 8), bh[nt][kt][1], bl[nt][kt][1]);
            }
        }
    }
    __syncthreads();

    const uint32_t sbase = smem_u32_(xp);
    const int krow_off = (lane & 7) + ((lane >> 4) << 3);
    const int bcol     = ((lane >> 3) & 1) << 3;
    const int mwbase   = wm * 64 + bcol;

    // bias / t-weight per n-pair (col = hl0 + wn*16 + nt*8 + (lane&3)*2)
    float2 bias2[2], tw2[2];
    #pragma unroll
    for (int nt = 0; nt < 2; nt++) {
        const int cg = hl0 + wn * 16 + nt * 8 + (lane & 3) * 2;
        bias2[nt] = *(const float2*)(bptr + cg);
        tw2[nt]   = (tptr != nullptr) ? *(const float2*)(tptr + cg) : make_float2(0.f, 0.f);
    }
    float* outg = &g_pre[gate][0];

    #pragma unroll 1
    for (int half = 0; half < 2; half++) {
        float acc[2][2][4];
        #pragma unroll
        for (int mt = 0; mt < 2; mt++)
            #pragma unroll
            for (int nt = 0; nt < 2; nt++) {
                acc[mt][nt][0] = 0.f; acc[mt][nt][1] = 0.f;
                acc[mt][nt][2] = 0.f; acc[mt][nt][3] = 0.f;
            }

        #pragma unroll
        for (int kt = 0; kt < 8; kt++) {
            #pragma unroll
            for (int mt = 0; mt < 2; mt++) {
                const int mtg = half * 2 + mt;
                const uint32_t addr = sbase
                    + 2u * (uint32_t)((kt * 16 + krow_off) * XP_STRIDE + mwbase + mtg * 16);
                uint32_t ah[4], al[4];
                ldsm4t_(ah, addr);
                ldsm4t_(al, addr + 2u * PLANE_HALVES);
                #pragma unroll
                for (int nt = 0; nt < 2; nt++) {
                    mma16816_(acc[mt][nt], ah, bh[nt][kt]);
                    mma16816_(acc[mt][nt], al, bh[nt][kt]);
                    mma16816_(acc[mt][nt], ah, bl[nt][kt]);
                }
            }
        }

        // Epilogue: bias / t terms / activations; store float2 to g_pre.
        #pragma unroll
        for (int mt = 0; mt < 2; mt++) {
            const int mtg = half * 2 + mt;
            const int r0 = bn0 + wm * 64 + mtg * 16 + (lane >> 2);
            const int r1 = r0 + 8;
            float tv0 = 0.f, tv1 = 0.f;
            if (gate >= 3) { tv0 = tvec[r0]; tv1 = tvec[r1]; }
            #pragma unroll
            for (int nt = 0; nt < 2; nt++) {
                const int cg = hl0 + wn * 16 + nt * 8 + (lane & 3) * 2;
                const float* a = acc[mt][nt];
                float2 o0, o1;
                if (gate < 3) {
                    o0 = make_float2(a[0] + bias2[nt].x, a[1] + bias2[nt].y);
                    o1 = make_float2(a[2] + bias2[nt].x, a[3] + bias2[nt].y);
                } else if (gate == 3) {
                    o0 = make_float2(a[0] + tw2[nt].x * tv0 + bias2[nt].x,
                                     a[1] + tw2[nt].y * tv0 + bias2[nt].y);
                    o1 = make_float2(a[2] + tw2[nt].x * tv1 + bias2[nt].x,
                                     a[3] + tw2[nt].y * tv1 + bias2[nt].y);
                } else {
                    o0 = make_float2(sigmoidf_(a[0] + tanh_fast_(tw2[nt].x * tv0) + bias2[nt].x),
                                     sigmoidf_(a[1] + tanh_fast_(tw2[nt].y * tv0) + bias2[nt].y));
                    o1 = make_float2(sigmoidf_(a[2] + tanh_fast_(tw2[nt].x * tv1) + bias2[nt].x),
                                     sigmoidf_(a[3] + tanh_fast_(tw2[nt].y * tv1) + bias2[nt].y));
                }
                *(float2*)(outg + (size_t)r0 * 256 + cg) = o0;
                *(float2*)(outg + (size_t)r1 * 256 + cg) = o1;
            }
        }
    }
}

// ============================================================================
// Phase 2: recurrence — unchanged from R13 (2121 us measured).
// ============================================================================

#define REC_THREADS 512
#define HBUF_B   0        // half [par 2][plane 2][k 256][b 16] = 32768 B
#define STG_B    32768    // half [par 2][plane 2][j 32][b 16] = 4096 B
#define CRED_B   36864    // float [kg 4][b 8][136] = 17408 B
#define MBAR_B   54272    // 2 x u64
#define SMEM_REC_BYTES 54400

__global__ void __cluster_dims__(8, 1, 1) __launch_bounds__(REC_THREADS, 1) lstm_rec_kernel(
    const float* __restrict__ fg_w_c, const float* __restrict__ fg_w_h,
    const float* __restrict__ ig_w_c, const float* __restrict__ ig_w_h,
    const float* __restrict__ in_w_h,
    const float* __restrict__ og_w_cn, const float* __restrict__ og_w_h,
    float* __restrict__ out)
{
    extern __shared__ char smc[];
    __half* Sg   = (__half*)(smc + STG_B);
    float*  Cred = (float*)(smc + CRED_B);

    const int tid  = threadIdx.x;
    const int lane = tid & 31;
    const int w    = tid >> 5;         // 0..15
    const int r    = blockIdx.x & 7;
    const int grp  = blockIdx.x >> 3;
    const int ns   = w & 3;            // n-slice (32 cols)
    const int kg   = w >> 2;           // k-group (64 k)

    const uint32_t sbase = smem_u32_(smc);
    const uint32_t mb0 = sbase + MBAR_B;
    const uint32_t mb1 = mb0 + 8;

    uint32_t bh[4][4][2], bl[4][4][2];   // [nt][kt][pair]
    {
        const float* Wg0[4] = { ig_w_h, fg_w_h, in_w_h, og_w_h };
        #pragma unroll
        for (int nt = 0; nt < 4; nt++) {
            const int n  = ns * 32 + nt * 8 + (lane >> 2);
            const float* Wr = Wg0[n >> 5] + (size_t)(r * 32 + (n & 31)) * 256;
            #pragma unroll
            for (int kt = 0; kt < 4; kt++) {
                const int kb = kg * 64 + kt * 16 + (lane & 3) * 2;
                float2 v0 = *(const float2*)(Wr + kb);
                float2 v1 = *(const float2*)(Wr + kb + 8);
                split2_(v0, bh[nt][kt][0], bl[nt][kt][0]);
                split2_(v1, bh[nt][kt][1], bl[nt][kt][1]);
            }
        }
    }

    for (int i = tid; i < 9216; i += REC_THREADS) ((uint32_t*)smc)[i] = 0u;

    if (tid == 0) {
        MBAR_INIT_(mb0, 1);
        MBAR_INIT_(mb1, 1);
        MBAR_ARRIVE_EXPECT_(mb0, 16384);
        MBAR_ARRIVE_EXPECT_(mb1, 16384);
    }

    const int b_own = w;
    const int j_own = lane;
    const int jg    = r * 32 + j_own;
    const int bg    = grp * 8 + b_own;
    const float wc_ig = ig_w_c[jg];
    const float wc_fg = fg_w_c[jg];
    const float wc_og = og_w_cn[jg];
    const size_t rowoff = (size_t)bg * Nv * 256 + jg;

    __syncthreads();
    CLUSTER_SYNC_();

    float cmv = 0.0f, hnv = 0.0f;
    uint32_t ph0 = 0, ph1 = 0;

    float p0 = 0.f, p1 = 0.f, p2 = 0.f, p3 = 0.f, p4 = 0.f, p5 = 0.f;
    if (tid < 256) {
        p0 = __ldcs(&g_pre[0][rowoff]);
        p1 = __ldcs(&g_pre[1][rowoff]);
        p2 = __ldcs(&g_pre[2][rowoff]);
        p3 = __ldcs(&g_pre[3][rowoff]);
        p4 = __ldcs(&g_pre[4][rowoff]);
        p5 = __ldcs(&g_pre[5][rowoff]);
    }

    const int krow_off = (lane & 7) + ((lane >> 4) << 3);
    const int bcol     = ((lane >> 3) & 1) << 3;

    #pragma unroll 1
    for (int n = 0; n < Nv; ++n) {
        const int q = n & 1;

        if (n != 0) {
            const uint32_t mb = q ? mb1 : mb0;
            mbar_wait_(mb, q ? ph1 : ph0);
            if (q) ph1 ^= 1; else ph0 ^= 1;
            if (tid == 0) MBAR_ARRIVE_EXPECT_(mb, 16384);
        }

        float q0 = 0.f, q1 = 0.f, q2 = 0.f, q3 = 0.f, q4 = 0.f, q5 = 0.f;
        if (tid < 256 && n + 1 < Nv) {
            const size_t off = rowoff + (size_t)(n + 1) * 256;
            q0 = __ldcs(&g_pre[0][off]); q1 = __ldcs(&g_pre[1][off]);
            q2 = __ldcs(&g_pre[2][off]); q3 = __ldcs(&g_pre[3][off]);
            q4 = __ldcs(&g_pre[4][off]); q5 = __ldcs(&g_pre[5][off]);
        }

        float c[4][4];
        #pragma unroll
        for (int nt = 0; nt < 4; nt++) { c[nt][0] = 0.f; c[nt][1] = 0.f; c[nt][2] = 0.f; c[nt][3] = 0.f; }

        #pragma unroll
        for (int kt = 0; kt < 4; kt++) {
            const uint32_t hbase = (uint32_t)(q * 8192 + (kg * 64 + kt * 16 + krow_off) * 16 + bcol);
            uint32_t ah[4], al[4];
            ldsm4t_(ah, sbase + HBUF_B + 2u * hbase);
            ldsm4t_(al, sbase + HBUF_B + 2u * (hbase + 4096));
            #pragma unroll
            for (int nt = 0; nt < 4; nt++) {
                mma16816_(c[nt], ah, bh[nt][kt]);
                mma16816_(c[nt], al, bh[nt][kt]);
                mma16816_(c[nt], ah, bl[nt][kt]);
            }
        }

        {
            const int bq = lane >> 2;
            #pragma unroll
            for (int nt = 0; nt < 4; nt++) {
                const int n0 = ns * 32 + nt * 8 + (lane & 3) * 2;
                *(float2*)&Cred[(kg * 8 + bq) * 136 + n0] = make_float2(c[nt][0], c[nt][1]);
            }
        }
        __syncthreads();

        if (tid < 256) {
            float s_ig = 0.f, s_fg = 0.f, s_in = 0.f, s_og = 0.f;
            #pragma unroll
            for (int kc = 0; kc < 4; kc++) {
                const float* rr = Cred + (kc * 8 + b_own) * 136 + j_own;
                s_ig += rr[0];
                s_fg += rr[32];
                s_in += rr[64];
                s_og += rr[96];
            }

            float ig  = sigmoidf_(wc_ig * cmv + s_ig + p1);
            float fg  = sigmoidf_(wc_fg * cmv + s_fg + p0);
            float inn = tanh_fast_(s_in + p2);
            float fc  = fg * cmv;
            float gi  = ig * inn;
            float cmh = fc + gi * p4;
            cmv       = fc + gi * p5;
            float og  = sigmoidf_(wc_og * cmh + s_og + p3);
            hnv       = og * tanh_fast_(cmh);

            if (n < Nv - 1) {
                const int qn = q ^ 1;
                __half hh = __float2half_rn(hnv);
                __half hl = __float2half_rn(hnv - __half2float(hh));
                Sg[qn * 1024 + 0 * 512 + j_own * 16 + b_own] = hh;
                Sg[qn * 1024 + 1 * 512 + j_own * 16 + b_own] = hl;
                BAR_SYNC_(1, 256);
                if (tid < 16) {
                    const uint32_t rk = (uint32_t)(tid & 7);
                    const uint32_t pl = (uint32_t)(tid >> 3);
                    FENCE_ASYNC_();
                    bulk_copy_rank_(
                        sbase + HBUF_B + 2u * (uint32_t)(qn * 8192 + pl * 4096 + (r * 32) * 16),
                        sbase + STG_B  + 2u * (uint32_t)(qn * 1024 + pl * 512),
                        qn ? mb1 : mb0, rk, 1024);
                }
            }
            p0 = q0; p1 = q1; p2 = q2; p3 = q3; p4 = q4; p5 = q5;
        }
    }

    CLUSTER_SYNC_();

    if (tid < 256) {
        out[(size_t)bg * 256 + jg]         = hnv;
        out[32768 + (size_t)bg * 256 + jg] = cmv;
    }
}

// ============================================================================
// Launch
// ============================================================================
extern "C" void kernel_launch(void* const* d_in, const int* in_sizes, int n_in,
                              void* d_out, int out_size)
{
    const float* x       = (const float*)d_in[0];
    const float* t       = (const float*)d_in[1];
    const float* fg_w_c  = (const float*)d_in[2];
    const float* fg_w_h  = (const float*)d_in[3];
    const float* fg_w_x  = (const float*)d_in[4];
    const float* fg_b    = (const float*)d_in[5];
    const float* ig_w_c  = (const float*)d_in[6];
    const float* ig_w_h  = (const float*)d_in[7];
    const float* ig_w_x  = (const float*)d_in[8];
    const float* ig_b    = (const float*)d_in[9];
    const float* in_w_h  = (const float*)d_in[10];
    const float* in_w_x  = (const float*)d_in[11];
    const float* in_b    = (const float*)d_in[12];
    const float* og_w_cn = (const float*)d_in[13];
    const float* og_w_h  = (const float*)d_in[14];
    const float* og_w_x  = (const float*)d_in[15];
    const float* og_b    = (const float*)d_in[16];
    const float* og_w_t  = (const float*)d_in[17];
    const float* tg1_w_x = (const float*)d_in[18];
    const float* tg1_w_t = (const float*)d_in[19];
    const float* tg1_b   = (const float*)d_in[20];
    const float* tg2_w_x = (const float*)d_in[21];
    const float* tg2_w_t = (const float*)d_in[22];
    const float* tg2_b   = (const float*)d_in[23];
    float* out = (float*)d_out;

    cudaFuncSetAttribute(precompute_kernel, cudaFuncAttributeMaxDynamicSharedMemorySize, PC_SMEM_BYTES);
    cudaFuncSetAttribute(lstm_rec_kernel,   cudaFuncAttributeMaxDynamicSharedMemorySize, SMEM_REC_BYTES);

    dim3 gp(512, 24);
    precompute_kernel<<<gp, 256, PC_SMEM_BYTES>>>(
        x, t,
        fg_w_x, fg_b, ig_w_x, ig_b, in_w_x, in_b,
        og_w_x, og_b, og_w_t,
        tg1_w_x, tg1_b, tg1_w_t,
        tg2_w_x, tg2_b, tg2_w_t);

    lstm_rec_kernel<<<128, REC_THREADS, SMEM_REC_BYTES>>>(
        fg_w_c, fg_w_h, ig_w_c, ig_w_h, in_w_h, og_w_cn, og_w_h, out);
}

// round 15
// speedup vs baseline: 1.5409x; 1.2677x over previous
#include <cuda_runtime.h>
#include <cuda_fp16.h>
#include <cstdint>

#define Bv 128
#define Nv 512
#define Xv 128
#define Hv 256
#define BN (Bv*Nv)           // 65536
#define GSZ (BN*Hv)          // 16777216 floats per gate buffer

// 6 precomputed gate-input buffers: 0=fg_x 1=ig_x 2=in_x 3=og_x 4=tm1 5=tm2
__device__ float g_pre[6][GSZ];

__device__ __forceinline__ float sigmoidf_(float v) { return 1.0f / (1.0f + __expf(-v)); }

// exp-based tanh: ~5 instr, rel err ~1e-6. Args bounded, no overflow path.
__device__ __forceinline__ float tanh_fast_(float x) {
    float e = __expf(-2.0f * x);
    return __fdividef(1.0f - e, 1.0f + e);
}

__device__ __forceinline__ uint32_t smem_u32_(const void* p) {
    uint32_t a;
    asm("{ .reg .u64 t; cvta.to.shared.u64 t, %1; cvt.u32.u64 %0, t; }" : "=r"(a) : "l"(p));
    return a;
}

// ---- tensor-core helpers ----
__device__ __forceinline__ void ldsm4t_(uint32_t* d, uint32_t addr) {
    asm volatile("ldmatrix.sync.aligned.m8n8.x4.trans.shared.b16 {%0,%1,%2,%3}, [%4];"
        : "=r"(d[0]), "=r"(d[1]), "=r"(d[2]), "=r"(d[3]) : "r"(addr));
}
__device__ __forceinline__ void mma16816_(float* c, const uint32_t* a, const uint32_t* b) {
    asm volatile(
        "mma.sync.aligned.m16n8k16.row.col.f32.f16.f16.f32 "
        "{%0,%1,%2,%3}, {%4,%5,%6,%7}, {%8,%9}, {%0,%1,%2,%3};"
        : "+f"(c[0]), "+f"(c[1]), "+f"(c[2]), "+f"(c[3])
        : "r"(a[0]), "r"(a[1]), "r"(a[2]), "r"(a[3]), "r"(b[0]), "r"(b[1]));
}
// Split fp32 pair into hi-fp16x2 and lo-residual-fp16x2.
__device__ __forceinline__ void split2_(float2 v, uint32_t& hi, uint32_t& lo) {
    __half h0 = __float2half_rn(v.x), h1 = __float2half_rn(v.y);
    float r0 = v.x - __half2float(h0), r1 = v.y - __half2float(h1);
    __half2 H = __halves2half2(h0, h1);
    __half2 L = __floats2half2_rn(r0, r1);
    hi = *(uint32_t*)&H;
    lo = *(uint32_t*)&L;
}

// Bulk DSMEM copy: local smem src -> rank rk's smem dst (same-offset address
// space), crediting rank rk's mbarrier with complete_tx bytes.
__device__ __forceinline__ void bulk_copy_rank_(uint32_t dst, uint32_t src,
                                                uint32_t mb, uint32_t rank,
                                                uint32_t bytes) {
    asm volatile(
        "{\n\t"
        ".reg .b32 rd, rm;\n\t"
        "mapa.shared::cluster.u32 rd, %0, %3;\n\t"
        "mapa.shared::cluster.u32 rm, %2, %3;\n\t"
        "cp.async.bulk.shared::cluster.shared::cta.mbarrier::complete_tx::bytes [rd], [%1], %4, [rm];\n\t"
        "}"
        :: "r"(dst), "r"(src), "r"(mb), "r"(rank), "r"(bytes) : "memory");
}

#define MBAR_INIT_(a, c) \
    asm volatile("mbarrier.init.shared.b64 [%0], %1;" :: "r"(a), "r"(c) : "memory")

#define MBAR_ARRIVE_EXPECT_(a, bytes) \
    asm volatile("mbarrier.arrive.expect_tx.shared.b64 _, [%0], %1;" \
                 :: "r"(a), "r"(bytes) : "memory")

#define FENCE_ASYNC_() asm volatile("fence.proxy.async.shared::cta;" ::: "memory")

__device__ __forceinline__ void mbar_wait_(uint32_t a, uint32_t parity) {
    asm volatile(
        "{\n\t"
        ".reg .pred P;\n\t"
        "WL_%=:\n\t"
        "mbarrier.try_wait.parity.acquire.cta.shared::cta.b64 P, [%0], %1, 0x989680;\n\t"
        "@P bra.uni WD_%=;\n\t"
        "bra.uni WL_%=;\n\t"
        "WD_%=:\n\t"
        "}"
        :: "r"(a), "r"(parity) : "memory");
}

#define CLUSTER_SYNC_() do { \
    asm volatile("barrier.cluster.arrive.aligned;" ::: "memory"); \
    asm volatile("barrier.cluster.wait.aligned;"   ::: "memory"); \
} while (0)

#define BAR_SYNC_(id, cnt) \
    asm volatile("bar.sync %0, %1;" :: "r"(id), "r"(cnt) : "memory")

// ============================================================================
// Phase 1: precompute, FUSED: one block per bn-tile converts x ONCE and loops
// over all 24 (gate, h-subtile) GEMMs. grid 512, block 256, 2 CTAs/SM.
// x k-major hi/lo planes [pl 2][k 128][m 136] (proven layout). Weight
// B-fragments re-loaded per tile from global (786 KB total -> L2-resident).
// mma body + epilogue identical to R14 (measured correct, rel_err 7.5e-7).
// ============================================================================

#define XP_STRIDE 136
#define PLANE_HALVES (128 * XP_STRIDE)          // 17408 halves
#define PC_SMEM_BYTES (2 * PLANE_HALVES * 2)    // 69632 B

__global__ void __launch_bounds__(256, 2) precompute_kernel(
    const float* __restrict__ x, const float* __restrict__ tvec,
    const float* __restrict__ fg_w_x, const float* __restrict__ fg_b,
    const float* __restrict__ ig_w_x, const float* __restrict__ ig_b,
    const float* __restrict__ in_w_x, const float* __restrict__ in_b,
    const float* __restrict__ og_w_x, const float* __restrict__ og_b, const float* __restrict__ og_w_t,
    const float* __restrict__ tg1_w_x, const float* __restrict__ tg1_b, const float* __restrict__ tg1_w_t,
    const float* __restrict__ tg2_w_x, const float* __restrict__ tg2_b, const float* __restrict__ tg2_w_t)
{
    extern __shared__ __half xp[];   // [plane 2][k 128][m 136]

    const int tid  = threadIdx.x;
    const int lane = tid & 31;
    const int w    = tid >> 5;       // 0..7
    const int bn0  = blockIdx.x * 128;

    // Convert x tile [128 m][128 k] fp32 -> k-major hi/lo planes (ONCE).
    for (int i = tid; i < 4096; i += 256) {
        const int m  = i >> 5;
        const int kq = i & 31;
        float4 v = *(const float4*)(x + (size_t)(bn0 + m) * 128 + kq * 4);
        const float vv[4] = { v.x, v.y, v.z, v.w };
        #pragma unroll
        for (int s = 0; s < 4; s++) {
            const int k = kq * 4 + s;
            __half hh = __float2half_rn(vv[s]);
            xp[k * XP_STRIDE + m]                = hh;
            xp[PLANE_HALVES + k * XP_STRIDE + m] = __float2half_rn(vv[s] - __half2float(hh));
        }
    }
    __syncthreads();

    const uint32_t sbase = smem_u32_(xp);
    const int wm = w & 1;    // m half (64 rows)
    const int wn = w >> 1;   // n quarter (16 cols)
    const int krow_off = (lane & 7) + ((lane >> 4) << 3);
    const int bcol     = ((lane >> 3) & 1) << 3;
    const int mwbase   = wm * 64 + bcol;

    // tvec rows for this warp's m half (gate >= 3 only), hoisted.
    float tv[2][2];   // [mtg>>1? no: index by (mtg, which of r0/r1)] -> compute per mtg
    // (loaded lazily below per tile loop; cheap L1 hits)

    #pragma unroll 1
    for (int ht = 0; ht < 24; ++ht) {
        const int gate = ht >> 2;
        const int hl0  = (ht & 3) * 64;

        const float* wptr; const float* bptr; const float* tptr = nullptr;
        switch (gate) {
            case 0:  wptr = fg_w_x;  bptr = fg_b;  break;
            case 1:  wptr = ig_w_x;  bptr = ig_b;  break;
            case 2:  wptr = in_w_x;  bptr = in_b;  break;
            case 3:  wptr = og_w_x;  bptr = og_b;  tptr = og_w_t;  break;
            case 4:  wptr = tg1_w_x; bptr = tg1_b; tptr = tg1_w_t; break;
            default: wptr = tg2_w_x; bptr = tg2_b; tptr = tg2_w_t; break;
        }

        // W B-fragments in registers: [nt 2][kt 8][pair 2], hi + lo (L2 hits).
        uint32_t bh[2][8][2], bl[2][8][2];
        #pragma unroll
        for (int nt = 0; nt < 2; nt++) {
            const int n = hl0 + wn * 16 + nt * 8 + (lane >> 2);
            const float* Wr = wptr + (size_t)n * 128;
            #pragma unroll
            for (int kt = 0; kt < 8; kt++) {
                const int kb = kt * 16 + (lane & 3) * 2;
                split2_(*(const float2*)(Wr + kb),     bh[nt][kt][0], bl[nt][kt][0]);
                split2_(*(const float2*)(Wr + kb + 8), bh[nt][kt][1], bl[nt][kt][1]);
            }
        }

        float2 bias2[2], tw2[2];
        #pragma unroll
        for (int nt = 0; nt < 2; nt++) {
            const int cg = hl0 + wn * 16 + nt * 8 + (lane & 3) * 2;
            bias2[nt] = *(const float2*)(bptr + cg);
            tw2[nt]   = (tptr != nullptr) ? *(const float2*)(tptr + cg) : make_float2(0.f, 0.f);
        }
        float* outg = &g_pre[gate][0];

        #pragma unroll 1
        for (int half = 0; half < 2; half++) {
            float acc[2][2][4];
            #pragma unroll
            for (int mt = 0; mt < 2; mt++)
                #pragma unroll
                for (int nt = 0; nt < 2; nt++) {
                    acc[mt][nt][0] = 0.f; acc[mt][nt][1] = 0.f;
                    acc[mt][nt][2] = 0.f; acc[mt][nt][3] = 0.f;
                }

            #pragma unroll
            for (int kt = 0; kt < 8; kt++) {
                #pragma unroll
                for (int mt = 0; mt < 2; mt++) {
                    const int mtg = half * 2 + mt;
                    const uint32_t addr = sbase
                        + 2u * (uint32_t)((kt * 16 + krow_off) * XP_STRIDE + mwbase + mtg * 16);
                    uint32_t ah[4], al[4];
                    ldsm4t_(ah, addr);
                    ldsm4t_(al, addr + 2u * PLANE_HALVES);
                    #pragma unroll
                    for (int nt = 0; nt < 2; nt++) {
                        mma16816_(acc[mt][nt], ah, bh[nt][kt]);
                        mma16816_(acc[mt][nt], al, bh[nt][kt]);
                        mma16816_(acc[mt][nt], ah, bl[nt][kt]);
                    }
                }
            }

            // Epilogue: bias / t terms / activations; float2 stores to g_pre.
            #pragma unroll
            for (int mt = 0; mt < 2; mt++) {
                const int mtg = half * 2 + mt;
                const int r0 = bn0 + wm * 64 + mtg * 16 + (lane >> 2);
                const int r1 = r0 + 8;
                float tv0 = 0.f, tv1 = 0.f;
                if (gate >= 3) { tv0 = tvec[r0]; tv1 = tvec[r1]; }
                #pragma unroll
                for (int nt = 0; nt < 2; nt++) {
                    const int cg = hl0 + wn * 16 + nt * 8 + (lane & 3) * 2;
                    const float* a = acc[mt][nt];
                    float2 o0, o1;
                    if (gate < 3) {
                        o0 = make_float2(a[0] + bias2[nt].x, a[1] + bias2[nt].y);
                        o1 = make_float2(a[2] + bias2[nt].x, a[3] + bias2[nt].y);
                    } else if (gate == 3) {
                        o0 = make_float2(a[0] + tw2[nt].x * tv0 + bias2[nt].x,
                                         a[1] + tw2[nt].y * tv0 + bias2[nt].y);
                        o1 = make_float2(a[2] + tw2[nt].x * tv1 + bias2[nt].x,
                                         a[3] + tw2[nt].y * tv1 + bias2[nt].y);
                    } else {
                        o0 = make_float2(sigmoidf_(a[0] + tanh_fast_(tw2[nt].x * tv0) + bias2[nt].x),
                                         sigmoidf_(a[1] + tanh_fast_(tw2[nt].y * tv0) + bias2[nt].y));
                        o1 = make_float2(sigmoidf_(a[2] + tanh_fast_(tw2[nt].x * tv1) + bias2[nt].x),
                                         sigmoidf_(a[3] + tanh_fast_(tw2[nt].y * tv1) + bias2[nt].y));
                    }
                    *(float2*)(outg + (size_t)r0 * 256 + cg) = o0;
                    *(float2*)(outg + (size_t)r1 * 256 + cg) = o1;
                }
            }
        }
    }
}

// ============================================================================
// Phase 2: recurrence — unchanged from R13 (2116 us measured).
// ============================================================================

#define REC_THREADS 512
#define HBUF_B   0        // half [par 2][plane 2][k 256][b 16] = 32768 B
#define STG_B    32768    // half [par 2][plane 2][j 32][b 16] = 4096 B
#define CRED_B   36864    // float [kg 4][b 8][136] = 17408 B
#define MBAR_B   54272    // 2 x u64
#define SMEM_REC_BYTES 54400

__global__ void __cluster_dims__(8, 1, 1) __launch_bounds__(REC_THREADS, 1) lstm_rec_kernel(
    const float* __restrict__ fg_w_c, const float* __restrict__ fg_w_h,
    const float* __restrict__ ig_w_c, const float* __restrict__ ig_w_h,
    const float* __restrict__ in_w_h,
    const float* __restrict__ og_w_cn, const float* __restrict__ og_w_h,
    float* __restrict__ out)
{
    extern __shared__ char smc[];
    __half* Sg   = (__half*)(smc + STG_B);
    float*  Cred = (float*)(smc + CRED_B);

    const int tid  = threadIdx.x;
    const int lane = tid & 31;
    const int w    = tid >> 5;         // 0..15
    const int r    = blockIdx.x & 7;
    const int grp  = blockIdx.x >> 3;
    const int ns   = w & 3;            // n-slice (32 cols)
    const int kg   = w >> 2;           // k-group (64 k)

    const uint32_t sbase = smem_u32_(smc);
    const uint32_t mb0 = sbase + MBAR_B;
    const uint32_t mb1 = mb0 + 8;

    uint32_t bh[4][4][2], bl[4][4][2];   // [nt][kt][pair]
    {
        const float* Wg0[4] = { ig_w_h, fg_w_h, in_w_h, og_w_h };
        #pragma unroll
        for (int nt = 0; nt < 4; nt++) {
            const int n  = ns * 32 + nt * 8 + (lane >> 2);
            const float* Wr = Wg0[n >> 5] + (size_t)(r * 32 + (n & 31)) * 256;
            #pragma unroll
            for (int kt = 0; kt < 4; kt++) {
                const int kb = kg * 64 + kt * 16 + (lane & 3) * 2;
                float2 v0 = *(const float2*)(Wr + kb);
                float2 v1 = *(const float2*)(Wr + kb + 8);
                split2_(v0, bh[nt][kt][0], bl[nt][kt][0]);
                split2_(v1, bh[nt][kt][1], bl[nt][kt][1]);
            }
        }
    }

    for (int i = tid; i < 9216; i += REC_THREADS) ((uint32_t*)smc)[i] = 0u;

    if (tid == 0) {
        MBAR_INIT_(mb0, 1);
        MBAR_INIT_(mb1, 1);
        MBAR_ARRIVE_EXPECT_(mb0, 16384);
        MBAR_ARRIVE_EXPECT_(mb1, 16384);
    }

    const int b_own = w;
    const int j_own = lane;
    const int jg    = r * 32 + j_own;
    const int bg    = grp * 8 + b_own;
    const float wc_ig = ig_w_c[jg];
    const float wc_fg = fg_w_c[jg];
    const float wc_og = og_w_cn[jg];
    const size_t rowoff = (size_t)bg * Nv * 256 + jg;

    __syncthreads();
    CLUSTER_SYNC_();

    float cmv = 0.0f, hnv = 0.0f;
    uint32_t ph0 = 0, ph1 = 0;

    float p0 = 0.f, p1 = 0.f, p2 = 0.f, p3 = 0.f, p4 = 0.f, p5 = 0.f;
    if (tid < 256) {
        p0 = __ldcs(&g_pre[0][rowoff]);
        p1 = __ldcs(&g_pre[1][rowoff]);
        p2 = __ldcs(&g_pre[2][rowoff]);
        p3 = __ldcs(&g_pre[3][rowoff]);
        p4 = __ldcs(&g_pre[4][rowoff]);
        p5 = __ldcs(&g_pre[5][rowoff]);
    }

    const int krow_off = (lane & 7) + ((lane >> 4) << 3);
    const int bcol     = ((lane >> 3) & 1) << 3;

    #pragma unroll 1
    for (int n = 0; n < Nv; ++n) {
        const int q = n & 1;

        if (n != 0) {
            const uint32_t mb = q ? mb1 : mb0;
            mbar_wait_(mb, q ? ph1 : ph0);
            if (q) ph1 ^= 1; else ph0 ^= 1;
            if (tid == 0) MBAR_ARRIVE_EXPECT_(mb, 16384);
        }

        float q0 = 0.f, q1 = 0.f, q2 = 0.f, q3 = 0.f, q4 = 0.f, q5 = 0.f;
        if (tid < 256 && n + 1 < Nv) {
            const size_t off = rowoff + (size_t)(n + 1) * 256;
            q0 = __ldcs(&g_pre[0][off]); q1 = __ldcs(&g_pre[1][off]);
            q2 = __ldcs(&g_pre[2][off]); q3 = __ldcs(&g_pre[3][off]);
            q4 = __ldcs(&g_pre[4][off]); q5 = __ldcs(&g_pre[5][off]);
        }

        float c[4][4];
        #pragma unroll
        for (int nt = 0; nt < 4; nt++) { c[nt][0] = 0.f; c[nt][1] = 0.f; c[nt][2] = 0.f; c[nt][3] = 0.f; }

        #pragma unroll
        for (int kt = 0; kt < 4; kt++) {
            const uint32_t hbase = (uint32_t)(q * 8192 + (kg * 64 + kt * 16 + krow_off) * 16 + bcol);
            uint32_t ah[4], al[4];
            ldsm4t_(ah, sbase + HBUF_B + 2u * hbase);
            ldsm4t_(al, sbase + HBUF_B + 2u * (hbase + 4096));
            #pragma unroll
            for (int nt = 0; nt < 4; nt++) {
                mma16816_(c[nt], ah, bh[nt][kt]);
                mma16816_(c[nt], al, bh[nt][kt]);
                mma16816_(c[nt], ah, bl[nt][kt]);
            }
        }

        {
            const int bq = lane >> 2;
            #pragma unroll
            for (int nt = 0; nt < 4; nt++) {
                const int n0 = ns * 32 + nt * 8 + (lane & 3) * 2;
                *(float2*)&Cred[(kg * 8 + bq) * 136 + n0] = make_float2(c[nt][0], c[nt][1]);
            }
        }
        __syncthreads();

        if (tid < 256) {
            float s_ig = 0.f, s_fg = 0.f, s_in = 0.f, s_og = 0.f;
            #pragma unroll
            for (int kc = 0; kc < 4; kc++) {
                const float* rr = Cred + (kc * 8 + b_own) * 136 + j_own;
                s_ig += rr[0];
                s_fg += rr[32];
                s_in += rr[64];
                s_og += rr[96];
            }

            float ig  = sigmoidf_(wc_ig * cmv + s_ig + p1);
            float fg  = sigmoidf_(wc_fg * cmv + s_fg + p0);
            float inn = tanh_fast_(s_in + p2);
            float fc  = fg * cmv;
            float gi  = ig * inn;
            float cmh = fc + gi * p4;
            cmv       = fc + gi * p5;
            float og  = sigmoidf_(wc_og * cmh + s_og + p3);
            hnv       = og * tanh_fast_(cmh);

            if (n < Nv - 1) {
                const int qn = q ^ 1;
                __half hh = __float2half_rn(hnv);
                __half hl = __float2half_rn(hnv - __half2float(hh));
                Sg[qn * 1024 + 0 * 512 + j_own * 16 + b_own] = hh;
                Sg[qn * 1024 + 1 * 512 + j_own * 16 + b_own] = hl;
                BAR_SYNC_(1, 256);
                if (tid < 16) {
                    const uint32_t rk = (uint32_t)(tid & 7);
                    const uint32_t pl = (uint32_t)(tid >> 3);
                    FENCE_ASYNC_();
                    bulk_copy_rank_(
                        sbase + HBUF_B + 2u * (uint32_t)(qn * 8192 + pl * 4096 + (r * 32) * 16),
                        sbase + STG_B  + 2u * (uint32_t)(qn * 1024 + pl * 512),
                        qn ? mb1 : mb0, rk, 1024);
                }
            }
            p0 = q0; p1 = q1; p2 = q2; p3 = q3; p4 = q4; p5 = q5;
        }
    }

    CLUSTER_SYNC_();

    if (tid < 256) {
        out[(size_t)bg * 256 + jg]         = hnv;
        out[32768 + (size_t)bg * 256 + jg] = cmv;
    }
}

// ============================================================================
// Launch
// ============================================================================
extern "C" void kernel_launch(void* const* d_in, const int* in_sizes, int n_in,
                              void* d_out, int out_size)
{
    const float* x       = (const float*)d_in[0];
    const float* t       = (const float*)d_in[1];
    const float* fg_w_c  = (const float*)d_in[2];
    const float* fg_w_h  = (const float*)d_in[3];
    const float* fg_w_x  = (const float*)d_in[4];
    const float* fg_b    = (const float*)d_in[5];
    const float* ig_w_c  = (const float*)d_in[6];
    const float* ig_w_h  = (const float*)d_in[7];
    const float* ig_w_x  = (const float*)d_in[8];
    const float* ig_b    = (const float*)d_in[9];
    const float* in_w_h  = (const float*)d_in[10];
    const float* in_w_x  = (const float*)d_in[11];
    const float* in_b    = (const float*)d_in[12];
    const float* og_w_cn = (const float*)d_in[13];
    const float* og_w_h  = (const float*)d_in[14];
    const float* og_w_x  = (const float*)d_in[15];
    const float* og_b    = (const float*)d_in[16];
    const float* og_w_t  = (const float*)d_in[17];
    const float* tg1_w_x = (const float*)d_in[18];
    const float* tg1_w_t = (const float*)d_in[19];
    const float* tg1_b   = (const float*)d_in[20];
    const float* tg2_w_x = (const float*)d_in[21];
    const float* tg2_w_t = (const float*)d_in[22];
    const float* tg2_b   = (const float*)d_in[23];
    float* out = (float*)d_out;

    cudaFuncSetAttribute(precompute_kernel, cudaFuncAttributeMaxDynamicSharedMemorySize, PC_SMEM_BYTES);
    cudaFuncSetAttribute(lstm_rec_kernel,   cudaFuncAttributeMaxDynamicSharedMemorySize, SMEM_REC_BYTES);

    precompute_kernel<<<512, 256, PC_SMEM_BYTES>>>(
        x, t,
        fg_w_x, fg_b, ig_w_x, ig_b, in_w_x, in_b,
        og_w_x, og_b, og_w_t,
        tg1_w_x, tg1_b, tg1_w_t,
        tg2_w_x, tg2_b, tg2_w_t);

    lstm_rec_kernel<<<128, REC_THREADS, SMEM_REC_BYTES>>>(
        fg_w_c, fg_w_h, ig_w_c, ig_w_h, in_w_h, og_w_cn, og_w_h, out);
}